// round 4
// baseline (speedup 1.0000x reference)
#include <cuda_runtime.h>
#include <math.h>

#define T    512
#define H    2048
#define II   1024
#define E    64
#define KSEL 8

#define BM 32
#define BN 128
#define BK 32
#define PAD 4

// -------- device-global scratch (no allocations allowed) --------
__device__ int   g_cnt[E];
__device__ int   g_off[E];
__device__ int   g_tok[E * T];
__device__ float g_prob[E * T];
__device__ float g_act[(size_t)T * KSEL * II];   // 16 MB compact activation rows

// ======================= gating =======================
__global__ void gate_kernel(const float* __restrict__ x,
                            const float* __restrict__ Wgate)
{
    __shared__ float sx[H];
    __shared__ float slog[E];
    __shared__ int   s_ids[KSEL];
    __shared__ float s_p[KSEL];

    const int t   = blockIdx.x;
    const int tid = threadIdx.x;

    for (int i = tid; i < H; i += blockDim.x) sx[i] = x[(size_t)t * H + i];
    __syncthreads();

    const int w = tid >> 5, lane = tid & 31;
    // 8 warps x 8 experts each
    for (int j = 0; j < 8; j++) {
        const int e = w * 8 + j;
        const float* wr = Wgate + (size_t)e * H;
        float s = 0.f;
        for (int h = lane; h < H; h += 32) s += sx[h] * wr[h];
        #pragma unroll
        for (int o = 16; o > 0; o >>= 1) s += __shfl_xor_sync(0xffffffffu, s, o);
        if (lane == 0) slog[e] = s;
    }
    __syncthreads();

    if (tid == 0) {
        float vals[KSEL]; int ids[KSEL];
        for (int j = 0; j < KSEL; j++) {
            float best = -1e30f; int bi = 0;
            for (int e = 0; e < E; e++)
                if (slog[e] > best) { best = slog[e]; bi = e; }
            vals[j] = best; ids[j] = bi; slog[bi] = -1e30f;
        }
        const float m = vals[0];
        float sum = 0.f;
        for (int j = 0; j < KSEL; j++) { vals[j] = expf(vals[j] - m); sum += vals[j]; }
        const float inv = 1.f / sum;
        for (int j = 0; j < KSEL; j++) { s_ids[j] = ids[j]; s_p[j] = vals[j] * inv; }
    }
    __syncthreads();

    if (tid < KSEL) {
        const int e = s_ids[tid];
        const int pos = atomicAdd(&g_cnt[e], 1);
        g_tok[e * T + pos]  = t;
        g_prob[e * T + pos] = s_p[tid];
    }
}

__global__ void scan_kernel()
{
    if (threadIdx.x == 0) {
        int s = 0;
        for (int e = 0; e < E; e++) { g_off[e] = s; s += g_cnt[e]; }
    }
}

// ======================= gate/up GEMM + SwiGLU =======================
// C[m, n] over (tokens of expert e) x (I slice), K = H.
__global__ __launch_bounds__(256) void gateup_kernel(const float* __restrict__ x,
                                                     const float* __restrict__ Wg,
                                                     const float* __restrict__ Wu)
{
    const int e   = blockIdx.z;
    const int cnt = g_cnt[e];
    const int m0  = blockIdx.y * BM;
    if (m0 >= cnt) return;
    const int n0   = blockIdx.x * BN;
    const int base = g_off[e];

    __shared__ float As [BK][BM + PAD];
    __shared__ float Bgs[BK][BN + PAD];
    __shared__ float Bus[BK][BN + PAD];

    const int tid = threadIdx.x;
    const int lm  = tid >> 3;          // 0..31
    const int lk  = (tid & 7) << 2;    // 0,4,...,28

    const int tokm = min(m0 + lm, cnt - 1);
    const float* xrow = x + (size_t)g_tok[e * T + tokm] * H;
    const float* WgE  = Wg + ((size_t)e * II + n0) * H;
    const float* WuE  = Wu + ((size_t)e * II + n0) * H;

    const int tx = tid & 31;           // col group: n = tx*4 + c
    const int ty = tid >> 5;           // row group: m = ty*4 + r

    float cg[4][4] = {}, cu[4][4] = {};

    for (int k0 = 0; k0 < H; k0 += BK) {
        float4 av = *(const float4*)(xrow + k0 + lk);
        As[lk + 0][lm] = av.x; As[lk + 1][lm] = av.y;
        As[lk + 2][lm] = av.z; As[lk + 3][lm] = av.w;
        #pragma unroll
        for (int p = 0; p < 4; p++) {
            const int n = p * 32 + lm;
            float4 bv = *(const float4*)(WgE + (size_t)n * H + k0 + lk);
            Bgs[lk + 0][n] = bv.x; Bgs[lk + 1][n] = bv.y;
            Bgs[lk + 2][n] = bv.z; Bgs[lk + 3][n] = bv.w;
            float4 uv = *(const float4*)(WuE + (size_t)n * H + k0 + lk);
            Bus[lk + 0][n] = uv.x; Bus[lk + 1][n] = uv.y;
            Bus[lk + 2][n] = uv.z; Bus[lk + 3][n] = uv.w;
        }
        __syncthreads();
        #pragma unroll
        for (int kk = 0; kk < BK; kk++) {
            float4 a  = *(const float4*)&As [kk][ty * 4];
            float4 bg = *(const float4*)&Bgs[kk][tx * 4];
            float4 bu = *(const float4*)&Bus[kk][tx * 4];
            const float ar[4]  = {a.x,  a.y,  a.z,  a.w};
            const float bgr[4] = {bg.x, bg.y, bg.z, bg.w};
            const float bur[4] = {bu.x, bu.y, bu.z, bu.w};
            #pragma unroll
            for (int r = 0; r < 4; r++)
                #pragma unroll
                for (int c = 0; c < 4; c++) {
                    cg[r][c] += ar[r] * bgr[c];
                    cu[r][c] += ar[r] * bur[c];
                }
        }
        __syncthreads();
    }

    #pragma unroll
    for (int r = 0; r < 4; r++) {
        const int m = ty * 4 + r;
        if (m0 + m >= cnt) continue;
        const float p = g_prob[e * T + m0 + m];
        float* arow = g_act + (size_t)(base + m0 + m) * II + n0;
        #pragma unroll
        for (int c = 0; c < 4; c++) {
            const float hg = cg[r][c], hu = cu[r][c];
            arow[tx * 4 + c] = hg / (1.f + expf(-hg)) * hu * p;
        }
    }
}

// ======================= down GEMM + scatter-accumulate =======================
// out[t, n] += sum_k act[row, k] * Wd[e, n, k];  N over H, K = I.
__global__ __launch_bounds__(256) void down_kernel(const float* __restrict__ Wd,
                                                   float* __restrict__ out)
{
    const int e   = blockIdx.z;
    const int cnt = g_cnt[e];
    const int m0  = blockIdx.y * BM;
    if (m0 >= cnt) return;
    const int n0   = blockIdx.x * BN;
    const int base = g_off[e];

    __shared__ float As[BK][BM + PAD];
    __shared__ float Bs[BK][BN + PAD];

    const int tid = threadIdx.x;
    const int lm  = tid >> 3;
    const int lk  = (tid & 7) << 2;

    const int row = base + min(m0 + lm, cnt - 1);
    const float* arowg = g_act + (size_t)row * II;
    const float* WdE   = Wd + ((size_t)e * H + n0) * II;

    const int tx = tid & 31;
    const int ty = tid >> 5;

    float acc[4][4] = {};

    for (int k0 = 0; k0 < II; k0 += BK) {
        float4 av = *(const float4*)(arowg + k0 + lk);
        As[lk + 0][lm] = av.x; As[lk + 1][lm] = av.y;
        As[lk + 2][lm] = av.z; As[lk + 3][lm] = av.w;
        #pragma unroll
        for (int p = 0; p < 4; p++) {
            const int n = p * 32 + lm;
            float4 bv = *(const float4*)(WdE + (size_t)n * II + k0 + lk);
            Bs[lk + 0][n] = bv.x; Bs[lk + 1][n] = bv.y;
            Bs[lk + 2][n] = bv.z; Bs[lk + 3][n] = bv.w;
        }
        __syncthreads();
        #pragma unroll
        for (int kk = 0; kk < BK; kk++) {
            float4 a = *(const float4*)&As[kk][ty * 4];
            float4 b = *(const float4*)&Bs[kk][tx * 4];
            const float ar[4] = {a.x, a.y, a.z, a.w};
            const float br[4] = {b.x, b.y, b.z, b.w};
            #pragma unroll
            for (int r = 0; r < 4; r++)
                #pragma unroll
                for (int c = 0; c < 4; c++)
                    acc[r][c] += ar[r] * br[c];
        }
        __syncthreads();
    }

    #pragma unroll
    for (int r = 0; r < 4; r++) {
        const int m = ty * 4 + r;
        if (m0 + m >= cnt) continue;
        const int t = g_tok[e * T + m0 + m];
        float* orow = out + (size_t)t * H + n0;
        #pragma unroll
        for (int c = 0; c < 4; c++)
            atomicAdd(&orow[tx * 4 + c], acc[r][c]);
    }
}

// ======================= launch =======================
extern "C" void kernel_launch(void* const* d_in, const int* in_sizes, int n_in,
                              void* d_out, int out_size)
{
    const float* x     = (const float*)d_in[0];
    const float* Wg    = (const float*)d_in[1];
    const float* Wu    = (const float*)d_in[2];
    const float* Wd    = (const float*)d_in[3];
    const float* Wgate = (const float*)d_in[4];
    float* out = (float*)d_out;

    void* cnt_ptr = nullptr;
    cudaGetSymbolAddress(&cnt_ptr, g_cnt);
    cudaMemsetAsync(cnt_ptr, 0, E * sizeof(int));
    cudaMemsetAsync(d_out, 0, (size_t)T * H * sizeof(float));

    gate_kernel<<<T, 256>>>(x, Wgate);
    scan_kernel<<<1, 32>>>();

    dim3 g1(II / BN, T / BM, E);
    gateup_kernel<<<g1, 256>>>(x, Wg, Wu);

    dim3 g2(H / BN, T / BM, E);
    down_kernel<<<g2, 256>>>(Wd, out);
}

// round 5
// speedup vs baseline: 1.1445x; 1.1445x over previous
#include <cuda_runtime.h>
#include <math.h>

#define T    512
#define H    2048
#define II   1024
#define E    64
#define KSEL 8

// GEMM tiling
#define BM   64     // token rows per block
#define BK   16     // k-slice
#define BNI  64     // i-columns per block (gateup; x2 matrices)
#define BND  128    // h-columns per block (down)
#define PAD  4

// -------- device-global scratch (no allocations allowed) --------
__device__ int   g_cnt[E];
__device__ int   g_off[E];
__device__ int   g_tok[E * T];
__device__ float g_prob[E * T];
__device__ float g_act[(size_t)T * KSEL * II];   // 16 MB compact activation rows

// ======================= gating =======================
__global__ void gate_kernel(const float* __restrict__ x,
                            const float* __restrict__ Wgate)
{
    __shared__ float sx[H];
    __shared__ float slog[E];
    __shared__ int   s_ids[KSEL];
    __shared__ float s_p[KSEL];

    const int t   = blockIdx.x;
    const int tid = threadIdx.x;

    for (int i = tid; i < H; i += blockDim.x) sx[i] = x[(size_t)t * H + i];
    __syncthreads();

    const int w = tid >> 5, lane = tid & 31;
    for (int j = 0; j < 8; j++) {
        const int e = w * 8 + j;
        const float* wr = Wgate + (size_t)e * H;
        float s = 0.f;
        for (int h = lane; h < H; h += 32) s += sx[h] * wr[h];
        #pragma unroll
        for (int o = 16; o > 0; o >>= 1) s += __shfl_xor_sync(0xffffffffu, s, o);
        if (lane == 0) slog[e] = s;
    }
    __syncthreads();

    if (tid == 0) {
        float vals[KSEL]; int ids[KSEL];
        for (int j = 0; j < KSEL; j++) {
            float best = -1e30f; int bi = 0;
            for (int e = 0; e < E; e++)
                if (slog[e] > best) { best = slog[e]; bi = e; }
            vals[j] = best; ids[j] = bi; slog[bi] = -1e30f;
        }
        const float m = vals[0];
        float sum = 0.f;
        for (int j = 0; j < KSEL; j++) { vals[j] = expf(vals[j] - m); sum += vals[j]; }
        const float inv = 1.f / sum;
        for (int j = 0; j < KSEL; j++) { s_ids[j] = ids[j]; s_p[j] = vals[j] * inv; }
    }
    __syncthreads();

    if (tid < KSEL) {
        const int e = s_ids[tid];
        const int pos = atomicAdd(&g_cnt[e], 1);
        g_tok[e * T + pos]  = t;
        g_prob[e * T + pos] = s_p[tid];
    }
}

__global__ void scan_kernel()
{
    if (threadIdx.x == 0) {
        int s = 0;
        for (int e = 0; e < E; e++) { g_off[e] = s; s += g_cnt[e]; }
    }
}

// ======================= gate/up GEMM + SwiGLU (fused) =======================
// Block: 64 tokens x 64 i-values, both Wg and Wu. 128 threads.
// Per-thread micro-tile: 8(m) x 4(i) x 2(mats) = 64 FMA per kk for 64B of LDS.
__global__ __launch_bounds__(128) void gateup_kernel(const float* __restrict__ x,
                                                     const float* __restrict__ Wg,
                                                     const float* __restrict__ Wu)
{
    const int e   = blockIdx.z;
    const int cnt = g_cnt[e];
    const int m0  = blockIdx.y * BM;
    if (m0 >= cnt) return;
    const int i0   = blockIdx.x * BNI;
    const int base = g_off[e];

    __shared__ float As[BK][BM  + PAD];
    __shared__ float Bg[BK][BNI + PAD];
    __shared__ float Bu[BK][BNI + PAD];

    const int tid = threadIdx.x;
    const int lr  = tid >> 2;          // 0..31 : row within half-tile
    const int kq  = (tid & 3) << 2;    // 0,4,8,12 : k offset

    // Precompute gather pointers (row identities fixed across the K loop)
    const float* pA0 = x + (size_t)g_tok[e * T + min(m0 + lr,      cnt - 1)] * H + kq;
    const float* pA1 = x + (size_t)g_tok[e * T + min(m0 + lr + 32, cnt - 1)] * H + kq;
    const float* WgE = Wg + ((size_t)e * II + i0) * H;
    const float* WuE = Wu + ((size_t)e * II + i0) * H;
    const float* pG0 = WgE + (size_t)lr * H + kq;
    const float* pG1 = WgE + (size_t)(lr + 32) * H + kq;
    const float* pU0 = WuE + (size_t)lr * H + kq;
    const float* pU1 = WuE + (size_t)(lr + 32) * H + kq;

    const int ty = tid >> 4;   // 0..7  : m-group (8 rows each)
    const int tx = tid & 15;   // 0..15 : i-group (4 cols each)

    float cg[8][4] = {}, cu[8][4] = {};

    for (int k0 = 0; k0 < H; k0 += BK) {
        float4 a0 = *(const float4*)(pA0 + k0);
        float4 a1 = *(const float4*)(pA1 + k0);
        float4 g0 = *(const float4*)(pG0 + k0);
        float4 g1 = *(const float4*)(pG1 + k0);
        float4 u0 = *(const float4*)(pU0 + k0);
        float4 u1 = *(const float4*)(pU1 + k0);

        As[kq + 0][lr] = a0.x; As[kq + 1][lr] = a0.y;
        As[kq + 2][lr] = a0.z; As[kq + 3][lr] = a0.w;
        As[kq + 0][lr + 32] = a1.x; As[kq + 1][lr + 32] = a1.y;
        As[kq + 2][lr + 32] = a1.z; As[kq + 3][lr + 32] = a1.w;

        Bg[kq + 0][lr] = g0.x; Bg[kq + 1][lr] = g0.y;
        Bg[kq + 2][lr] = g0.z; Bg[kq + 3][lr] = g0.w;
        Bg[kq + 0][lr + 32] = g1.x; Bg[kq + 1][lr + 32] = g1.y;
        Bg[kq + 2][lr + 32] = g1.z; Bg[kq + 3][lr + 32] = g1.w;

        Bu[kq + 0][lr] = u0.x; Bu[kq + 1][lr] = u0.y;
        Bu[kq + 2][lr] = u0.z; Bu[kq + 3][lr] = u0.w;
        Bu[kq + 0][lr + 32] = u1.x; Bu[kq + 1][lr + 32] = u1.y;
        Bu[kq + 2][lr + 32] = u1.z; Bu[kq + 3][lr + 32] = u1.w;

        __syncthreads();
        #pragma unroll
        for (int kk = 0; kk < BK; kk++) {
            float4 aL = *(const float4*)&As[kk][ty * 8];
            float4 aH = *(const float4*)&As[kk][ty * 8 + 4];
            float4 gv = *(const float4*)&Bg[kk][tx * 4];
            float4 uv = *(const float4*)&Bu[kk][tx * 4];
            const float ar[8]  = {aL.x, aL.y, aL.z, aL.w, aH.x, aH.y, aH.z, aH.w};
            const float bgr[4] = {gv.x, gv.y, gv.z, gv.w};
            const float bur[4] = {uv.x, uv.y, uv.z, uv.w};
            #pragma unroll
            for (int r = 0; r < 8; r++)
                #pragma unroll
                for (int c = 0; c < 4; c++) {
                    cg[r][c] += ar[r] * bgr[c];
                    cu[r][c] += ar[r] * bur[c];
                }
        }
        __syncthreads();
    }

    #pragma unroll
    for (int r = 0; r < 8; r++) {
        const int m = ty * 8 + r;
        if (m0 + m >= cnt) continue;
        const float p = g_prob[e * T + m0 + m];
        float4 v;
        float hg, hu;
        hg = cg[r][0]; hu = cu[r][0]; v.x = hg / (1.f + expf(-hg)) * hu * p;
        hg = cg[r][1]; hu = cu[r][1]; v.y = hg / (1.f + expf(-hg)) * hu * p;
        hg = cg[r][2]; hu = cu[r][2]; v.z = hg / (1.f + expf(-hg)) * hu * p;
        hg = cg[r][3]; hu = cu[r][3]; v.w = hg / (1.f + expf(-hg)) * hu * p;
        *(float4*)(g_act + (size_t)(base + m0 + m) * II + i0 + tx * 4) = v;
    }
}

// ======================= down GEMM + scatter-accumulate =======================
// Block: 64 rows x 128 h-cols, 128 threads, 8x8 per-thread micro-tile.
__global__ __launch_bounds__(128) void down_kernel(const float* __restrict__ Wd,
                                                   float* __restrict__ out)
{
    const int e   = blockIdx.z;
    const int cnt = g_cnt[e];
    const int m0  = blockIdx.y * BM;
    if (m0 >= cnt) return;
    const int n0   = blockIdx.x * BND;
    const int base = g_off[e];

    __shared__ float As[BK][BM  + PAD];
    __shared__ float Bs[BK][BND + PAD];

    const int tid = threadIdx.x;
    const int lr  = tid >> 2;          // 0..31
    const int kq  = (tid & 3) << 2;    // 0,4,8,12

    const float* pA0 = g_act + (size_t)(base + min(m0 + lr,      cnt - 1)) * II + kq;
    const float* pA1 = g_act + (size_t)(base + min(m0 + lr + 32, cnt - 1)) * II + kq;
    const float* WdE = Wd + ((size_t)e * H + n0) * II;
    const float* pB0 = WdE + (size_t)lr * II + kq;
    const float* pB1 = WdE + (size_t)(lr + 32) * II + kq;
    const float* pB2 = WdE + (size_t)(lr + 64) * II + kq;
    const float* pB3 = WdE + (size_t)(lr + 96) * II + kq;

    const int ty = tid >> 4;   // 0..7  : m-group
    const int tx = tid & 15;   // 0..15 : n-group (8 cols each)

    float acc[8][8] = {};

    for (int k0 = 0; k0 < II; k0 += BK) {
        float4 a0 = *(const float4*)(pA0 + k0);
        float4 a1 = *(const float4*)(pA1 + k0);
        float4 b0 = *(const float4*)(pB0 + k0);
        float4 b1 = *(const float4*)(pB1 + k0);
        float4 b2 = *(const float4*)(pB2 + k0);
        float4 b3 = *(const float4*)(pB3 + k0);

        As[kq + 0][lr] = a0.x; As[kq + 1][lr] = a0.y;
        As[kq + 2][lr] = a0.z; As[kq + 3][lr] = a0.w;
        As[kq + 0][lr + 32] = a1.x; As[kq + 1][lr + 32] = a1.y;
        As[kq + 2][lr + 32] = a1.z; As[kq + 3][lr + 32] = a1.w;

        Bs[kq + 0][lr] = b0.x; Bs[kq + 1][lr] = b0.y;
        Bs[kq + 2][lr] = b0.z; Bs[kq + 3][lr] = b0.w;
        Bs[kq + 0][lr + 32] = b1.x; Bs[kq + 1][lr + 32] = b1.y;
        Bs[kq + 2][lr + 32] = b1.z; Bs[kq + 3][lr + 32] = b1.w;
        Bs[kq + 0][lr + 64] = b2.x; Bs[kq + 1][lr + 64] = b2.y;
        Bs[kq + 2][lr + 64] = b2.z; Bs[kq + 3][lr + 64] = b2.w;
        Bs[kq + 0][lr + 96] = b3.x; Bs[kq + 1][lr + 96] = b3.y;
        Bs[kq + 2][lr + 96] = b3.z; Bs[kq + 3][lr + 96] = b3.w;

        __syncthreads();
        #pragma unroll
        for (int kk = 0; kk < BK; kk++) {
            float4 aL = *(const float4*)&As[kk][ty * 8];
            float4 aH = *(const float4*)&As[kk][ty * 8 + 4];
            float4 bL = *(const float4*)&Bs[kk][tx * 8];
            float4 bH = *(const float4*)&Bs[kk][tx * 8 + 4];
            const float ar[8] = {aL.x, aL.y, aL.z, aL.w, aH.x, aH.y, aH.z, aH.w};
            const float br[8] = {bL.x, bL.y, bL.z, bL.w, bH.x, bH.y, bH.z, bH.w};
            #pragma unroll
            for (int r = 0; r < 8; r++)
                #pragma unroll
                for (int c = 0; c < 8; c++)
                    acc[r][c] += ar[r] * br[c];
        }
        __syncthreads();
    }

    #pragma unroll
    for (int r = 0; r < 8; r++) {
        const int m = ty * 8 + r;
        if (m0 + m >= cnt) continue;
        const int t = g_tok[e * T + m0 + m];
        float* orow = out + (size_t)t * H + n0 + tx * 8;
        #pragma unroll
        for (int c = 0; c < 8; c++)
            atomicAdd(&orow[c], acc[r][c]);
    }
}

// ======================= launch =======================
extern "C" void kernel_launch(void* const* d_in, const int* in_sizes, int n_in,
                              void* d_out, int out_size)
{
    const float* x     = (const float*)d_in[0];
    const float* Wg    = (const float*)d_in[1];
    const float* Wu    = (const float*)d_in[2];
    const float* Wd    = (const float*)d_in[3];
    const float* Wgate = (const float*)d_in[4];
    float* out = (float*)d_out;

    void* cnt_ptr = nullptr;
    cudaGetSymbolAddress(&cnt_ptr, g_cnt);
    cudaMemsetAsync(cnt_ptr, 0, E * sizeof(int));
    cudaMemsetAsync(d_out, 0, (size_t)T * H * sizeof(float));

    gate_kernel<<<T, 256>>>(x, Wgate);
    scan_kernel<<<1, 32>>>();

    dim3 g1(II / BNI, T / BM, E);      // 16 x 8 x 64
    gateup_kernel<<<g1, 128>>>(x, Wg, Wu);

    dim3 g2(H / BND, T / BM, E);       // 16 x 8 x 64
    down_kernel<<<g2, 128>>>(Wd, out);
}

// round 7
// speedup vs baseline: 1.7073x; 1.4917x over previous
#include <cuda_runtime.h>
#include <cuda_bf16.h>
#include <stdint.h>
#include <math.h>

#define T    512
#define H    2048
#define II   1024
#define E    64
#define KSEL 8

#define BM   128
#define BK   32
#define PADK 40                      // padded k-stride (elems): 80B, 16B-aligned, ldmatrix conflict-free

// stage layout (bf16 elems). Both kernels use 4-5 regions of 128x40 / 64x40.
#define STG_ELEMS 20480              // 40960 B per stage
#define META_OFF  (2 * STG_ELEMS * 2)          // 81920 B
#define SMEM_DYN  (META_OFF + 2048)

// gateup regions (elem offsets)
#define GA_HI 0
#define GA_LO 5120
#define GG_HI 10240
#define GG_LO 12800
#define GU_HI 15360
#define GU_LO 17920
// down regions
#define DA_HI 0
#define DA_LO 5120
#define DB_HI 10240
#define DB_LO 15360

// -------- device-global scratch (no allocations allowed) --------
__device__ int   g_cnt[E];
__device__ int   g_off[E];
__device__ int   g_tok[E * T];
__device__ float g_prob[E * T];
__device__ float g_act[(size_t)T * KSEL * II];

// ======================= helpers =======================
__device__ __forceinline__ uint32_t smem_u32(const void* p) {
    uint32_t a;
    asm("{ .reg .u64 t; cvta.to.shared.u64 t, %1; cvt.u32.u64 %0, t; }" : "=r"(a) : "l"(p));
    return a;
}

__device__ __forceinline__ void ldm_x4(uint32_t r[4], uint32_t addr) {
    asm volatile("ldmatrix.sync.aligned.m8n8.x4.shared.b16 {%0,%1,%2,%3}, [%4];"
                 : "=r"(r[0]), "=r"(r[1]), "=r"(r[2]), "=r"(r[3]) : "r"(addr));
}
__device__ __forceinline__ void ldm_x2(uint32_t r[2], uint32_t addr) {
    asm volatile("ldmatrix.sync.aligned.m8n8.x2.shared.b16 {%0,%1}, [%2];"
                 : "=r"(r[0]), "=r"(r[1]) : "r"(addr));
}
__device__ __forceinline__ void mma_bf16(float d[4], const uint32_t a[4], const uint32_t b[2]) {
    asm volatile("mma.sync.aligned.m16n8k16.row.col.f32.bf16.bf16.f32 "
                 "{%0,%1,%2,%3}, {%4,%5,%6,%7}, {%8,%9}, {%0,%1,%2,%3};"
                 : "+f"(d[0]), "+f"(d[1]), "+f"(d[2]), "+f"(d[3])
                 : "r"(a[0]), "r"(a[1]), "r"(a[2]), "r"(a[3]), "r"(b[0]), "r"(b[1]));
}

// split fp32x4 -> bf16 hi/lo, store 8B each (padded layout, elem offset)
__device__ __forceinline__ void split_sts(__nv_bfloat16* hi, __nv_bfloat16* lo, float4 v) {
    __nv_bfloat16 h0 = __float2bfloat16(v.x), h1 = __float2bfloat16(v.y);
    __nv_bfloat16 h2 = __float2bfloat16(v.z), h3 = __float2bfloat16(v.w);
    __nv_bfloat16 l0 = __float2bfloat16(v.x - __bfloat162float(h0));
    __nv_bfloat16 l1 = __float2bfloat16(v.y - __bfloat162float(h1));
    __nv_bfloat16 l2 = __float2bfloat16(v.z - __bfloat162float(h2));
    __nv_bfloat16 l3 = __float2bfloat16(v.w - __bfloat162float(h3));
    uint2 hp, lp;
    hp.x = (uint32_t)__bfloat16_as_ushort(h0) | ((uint32_t)__bfloat16_as_ushort(h1) << 16);
    hp.y = (uint32_t)__bfloat16_as_ushort(h2) | ((uint32_t)__bfloat16_as_ushort(h3) << 16);
    lp.x = (uint32_t)__bfloat16_as_ushort(l0) | ((uint32_t)__bfloat16_as_ushort(l1) << 16);
    lp.y = (uint32_t)__bfloat16_as_ushort(l2) | ((uint32_t)__bfloat16_as_ushort(l3) << 16);
    *(uint2*)hi = hp;
    *(uint2*)lo = lp;
}

// ======================= gating =======================
__global__ void gate_kernel(const float* __restrict__ x,
                            const float* __restrict__ Wgate)
{
    __shared__ float sx[H];
    __shared__ float slog[E];
    __shared__ int   s_ids[KSEL];
    __shared__ float s_p[KSEL];

    const int t = blockIdx.x, tid = threadIdx.x;
    for (int i = tid; i < H; i += blockDim.x) sx[i] = x[(size_t)t * H + i];
    __syncthreads();

    const int w = tid >> 5, lane = tid & 31;
    for (int j = 0; j < 8; j++) {
        const int e = w * 8 + j;
        const float* wr = Wgate + (size_t)e * H;
        float s = 0.f;
        for (int h = lane; h < H; h += 32) s += sx[h] * wr[h];
        #pragma unroll
        for (int o = 16; o > 0; o >>= 1) s += __shfl_xor_sync(0xffffffffu, s, o);
        if (lane == 0) slog[e] = s;
    }
    __syncthreads();

    if (tid == 0) {
        float vals[KSEL]; int ids[KSEL];
        for (int j = 0; j < KSEL; j++) {
            float best = -1e30f; int bi = 0;
            for (int e = 0; e < E; e++)
                if (slog[e] > best) { best = slog[e]; bi = e; }
            vals[j] = best; ids[j] = bi; slog[bi] = -1e30f;
        }
        const float m = vals[0];
        float sum = 0.f;
        for (int j = 0; j < KSEL; j++) { vals[j] = expf(vals[j] - m); sum += vals[j]; }
        const float inv = 1.f / sum;
        for (int j = 0; j < KSEL; j++) { s_ids[j] = ids[j]; s_p[j] = vals[j] * inv; }
    }
    __syncthreads();

    if (tid < KSEL) {
        const int e = s_ids[tid];
        const int pos = atomicAdd(&g_cnt[e], 1);
        g_tok[e * T + pos]  = t;
        g_prob[e * T + pos] = s_p[tid];
    }
}

__global__ void scan_kernel()
{
    if (threadIdx.x == 0) {
        int s = 0;
        for (int e = 0; e < E; e++) { g_off[e] = s; s += g_cnt[e]; }
    }
}

// ======================= gate/up: mma.sync GEMM + SwiGLU =======================
// CTA: 128 tokens x 64 i-vals, both Wg & Wu. 8 warps 4(m)x2(i), warp 32m x 32i x 2 mats.
__global__ __launch_bounds__(256, 1) void gateup_mma(const float* __restrict__ x,
                                                     const float* __restrict__ Wg,
                                                     const float* __restrict__ Wu)
{
    extern __shared__ __align__(16) char smraw[];
    __nv_bfloat16* sm = (__nv_bfloat16*)smraw;

    const int e   = blockIdx.z;
    const int cnt = g_cnt[e];
    const int m0  = blockIdx.y * BM;
    if (m0 >= cnt) return;
    const int i0   = blockIdx.x * 64;
    const int base = g_off[e];
    const int tid = threadIdx.x, wid = tid >> 5, lane = tid & 31;

    int*   stok = (int*)(smraw + META_OFF);
    float* sp   = (float*)(smraw + META_OFF + 512);
    if (tid < BM) {
        const int mm = min(m0 + tid, cnt - 1);
        stok[tid] = g_tok[e * T + mm];
        sp[tid]   = (m0 + tid < cnt) ? g_prob[e * T + m0 + tid] : 0.f;
    }
    __syncthreads();

    const float* WgE = Wg + ((size_t)e * II + i0) * H;
    const float* WuE = Wu + ((size_t)e * II + i0) * H;

    const int wm = wid >> 1;   // 0..3
    const int wn = wid & 1;    // 0..1

    float ag[2][4][4] = {}, au[2][4][4] = {};
    float4 pa[4], pg[2], pu[2];

    const int NCH = H / BK;    // 64

    // prefetch stage 0
    {
        #pragma unroll
        for (int j = 0; j < 4; j++) {
            const int idx = tid + j * 256, r = idx >> 3, c = idx & 7;
            pa[j] = *(const float4*)(x + (size_t)stok[r] * H + c * 4);
        }
        #pragma unroll
        for (int j = 0; j < 2; j++) {
            const int idx = tid + j * 256, r = idx >> 3, c = idx & 7;
            pg[j] = *(const float4*)(WgE + (size_t)r * H + c * 4);
            pu[j] = *(const float4*)(WuE + (size_t)r * H + c * 4);
        }
        #pragma unroll
        for (int j = 0; j < 4; j++) {
            const int idx = tid + j * 256, off = (idx >> 3) * PADK + (idx & 7) * 4;
            split_sts(sm + GA_HI + off, sm + GA_LO + off, pa[j]);
        }
        #pragma unroll
        for (int j = 0; j < 2; j++) {
            const int idx = tid + j * 256, off = (idx >> 3) * PADK + (idx & 7) * 4;
            split_sts(sm + GG_HI + off, sm + GG_LO + off, pg[j]);
            split_sts(sm + GU_HI + off, sm + GU_LO + off, pu[j]);
        }
        __syncthreads();
    }

    for (int ch = 0; ch < NCH; ch++) {
        if (ch + 1 < NCH) {
            const int k0 = (ch + 1) * BK;
            #pragma unroll
            for (int j = 0; j < 4; j++) {
                const int idx = tid + j * 256, r = idx >> 3, c = idx & 7;
                pa[j] = *(const float4*)(x + (size_t)stok[r] * H + k0 + c * 4);
            }
            #pragma unroll
            for (int j = 0; j < 2; j++) {
                const int idx = tid + j * 256, r = idx >> 3, c = idx & 7;
                pg[j] = *(const float4*)(WgE + (size_t)r * H + k0 + c * 4);
                pu[j] = *(const float4*)(WuE + (size_t)r * H + k0 + c * 4);
            }
        }

        // compute on stage ch&1
        {
            const uint32_t sbase = smem_u32(sm + (ch & 1) * STG_ELEMS);
            #pragma unroll
            for (int k16 = 0; k16 < BK; k16 += 16) {
                uint32_t ah[2][4], al[2][4];
                #pragma unroll
                for (int mt = 0; mt < 2; mt++) {
                    const int row = wm * 32 + mt * 16 + (lane & 15);
                    const int col = k16 + ((lane >> 4) << 3);
                    const uint32_t off = (uint32_t)(row * PADK + col) * 2;
                    ldm_x4(ah[mt], sbase + GA_HI * 2 + off);
                    ldm_x4(al[mt], sbase + GA_LO * 2 + off);
                }
                #pragma unroll
                for (int it = 0; it < 4; it++) {
                    const int rowb = wn * 32 + it * 8 + (lane & 7);
                    const int colb = k16 + (((lane >> 3) & 1) << 3);
                    const uint32_t offb = (uint32_t)(rowb * PADK + colb) * 2;
                    uint32_t bgh[2], bgl[2], buh[2], bul[2];
                    ldm_x2(bgh, sbase + GG_HI * 2 + offb);
                    ldm_x2(bgl, sbase + GG_LO * 2 + offb);
                    ldm_x2(buh, sbase + GU_HI * 2 + offb);
                    ldm_x2(bul, sbase + GU_LO * 2 + offb);
                    #pragma unroll
                    for (int mt = 0; mt < 2; mt++) {
                        mma_bf16(ag[mt][it], ah[mt], bgh);
                        mma_bf16(ag[mt][it], ah[mt], bgl);
                        mma_bf16(ag[mt][it], al[mt], bgh);
                        mma_bf16(au[mt][it], ah[mt], buh);
                        mma_bf16(au[mt][it], ah[mt], bul);
                        mma_bf16(au[mt][it], al[mt], buh);
                    }
                }
            }
        }

        if (ch + 1 < NCH) {
            __nv_bfloat16* s = sm + ((ch + 1) & 1) * STG_ELEMS;
            #pragma unroll
            for (int j = 0; j < 4; j++) {
                const int idx = tid + j * 256, off = (idx >> 3) * PADK + (idx & 7) * 4;
                split_sts(s + GA_HI + off, s + GA_LO + off, pa[j]);
            }
            #pragma unroll
            for (int j = 0; j < 2; j++) {
                const int idx = tid + j * 256, off = (idx >> 3) * PADK + (idx & 7) * 4;
                split_sts(s + GG_HI + off, s + GG_LO + off, pg[j]);
                split_sts(s + GU_HI + off, s + GU_LO + off, pu[j]);
            }
        }
        __syncthreads();
    }

    // epilogue: silu(hg)*hu*p -> g_act
    #pragma unroll
    for (int mt = 0; mt < 2; mt++) {
        #pragma unroll
        for (int it = 0; it < 4; it++) {
            const int c  = i0 + wn * 32 + it * 8 + (lane & 3) * 2;
            const int r0 = wm * 32 + mt * 16 + (lane >> 2);
            #pragma unroll
            for (int hf = 0; hf < 2; hf++) {
                const int r = r0 + hf * 8;
                if (m0 + r < cnt) {
                    const float p = sp[r];
                    const float hg0 = ag[mt][it][hf * 2 + 0], hu0 = au[mt][it][hf * 2 + 0];
                    const float hg1 = ag[mt][it][hf * 2 + 1], hu1 = au[mt][it][hf * 2 + 1];
                    float2 v;
                    v.x = hg0 / (1.f + expf(-hg0)) * hu0 * p;
                    v.y = hg1 / (1.f + expf(-hg1)) * hu1 * p;
                    *(float2*)(g_act + (size_t)(base + m0 + r) * II + c) = v;
                }
            }
        }
    }
}

// ======================= down: mma.sync GEMM + scatter =======================
// CTA: 128 rows x 128 h-cols. 8 warps 4(m)x2(n), warp 32m x 64n.
__global__ __launch_bounds__(256, 1) void down_mma(const float* __restrict__ Wd,
                                                   float* __restrict__ out)
{
    extern __shared__ __align__(16) char smraw[];
    __nv_bfloat16* sm = (__nv_bfloat16*)smraw;

    const int e   = blockIdx.z;
    const int cnt = g_cnt[e];
    const int m0  = blockIdx.y * BM;
    if (m0 >= cnt) return;
    const int n0   = blockIdx.x * 128;
    const int base = g_off[e];
    const int tid = threadIdx.x, wid = tid >> 5, lane = tid & 31;

    int* stok = (int*)(smraw + META_OFF);
    int* srow = (int*)(smraw + META_OFF + 512);
    if (tid < BM) {
        const int mm = min(m0 + tid, cnt - 1);
        stok[tid] = g_tok[e * T + mm];
        srow[tid] = base + mm;
    }
    __syncthreads();

    const float* WdE = Wd + ((size_t)e * H + n0) * II;

    const int wm = wid >> 1;   // 0..3
    const int wn = wid & 1;    // 0..1

    float acc[2][8][4] = {};
    float4 pa[4], pb[4];

    const int NCH = II / BK;   // 32

    {
        #pragma unroll
        for (int j = 0; j < 4; j++) {
            const int idx = tid + j * 256, r = idx >> 3, c = idx & 7;
            pa[j] = *(const float4*)(g_act + (size_t)srow[r] * II + c * 4);
            pb[j] = *(const float4*)(WdE + (size_t)r * II + c * 4);
        }
        #pragma unroll
        for (int j = 0; j < 4; j++) {
            const int idx = tid + j * 256, off = (idx >> 3) * PADK + (idx & 7) * 4;
            split_sts(sm + DA_HI + off, sm + DA_LO + off, pa[j]);
            split_sts(sm + DB_HI + off, sm + DB_LO + off, pb[j]);
        }
        __syncthreads();
    }

    for (int ch = 0; ch < NCH; ch++) {
        if (ch + 1 < NCH) {
            const int k0 = (ch + 1) * BK;
            #pragma unroll
            for (int j = 0; j < 4; j++) {
                const int idx = tid + j * 256, r = idx >> 3, c = idx & 7;
                pa[j] = *(const float4*)(g_act + (size_t)srow[r] * II + k0 + c * 4);
                pb[j] = *(const float4*)(WdE + (size_t)r * II + k0 + c * 4);
            }
        }

        {
            const uint32_t sbase = smem_u32(sm + (ch & 1) * STG_ELEMS);
            #pragma unroll
            for (int k16 = 0; k16 < BK; k16 += 16) {
                uint32_t ah[2][4], al[2][4];
                #pragma unroll
                for (int mt = 0; mt < 2; mt++) {
                    const int row = wm * 32 + mt * 16 + (lane & 15);
                    const int col = k16 + ((lane >> 4) << 3);
                    const uint32_t off = (uint32_t)(row * PADK + col) * 2;
                    ldm_x4(ah[mt], sbase + DA_HI * 2 + off);
                    ldm_x4(al[mt], sbase + DA_LO * 2 + off);
                }
                #pragma unroll
                for (int nt = 0; nt < 8; nt++) {
                    const int rowb = wn * 64 + nt * 8 + (lane & 7);
                    const int colb = k16 + (((lane >> 3) & 1) << 3);
                    const uint32_t offb = (uint32_t)(rowb * PADK + colb) * 2;
                    uint32_t bh[2], bl[2];
                    ldm_x2(bh, sbase + DB_HI * 2 + offb);
                    ldm_x2(bl, sbase + DB_LO * 2 + offb);
                    #pragma unroll
                    for (int mt = 0; mt < 2; mt++) {
                        mma_bf16(acc[mt][nt], ah[mt], bh);
                        mma_bf16(acc[mt][nt], ah[mt], bl);
                        mma_bf16(acc[mt][nt], al[mt], bh);
                    }
                }
            }
        }

        if (ch + 1 < NCH) {
            __nv_bfloat16* s = sm + ((ch + 1) & 1) * STG_ELEMS;
            #pragma unroll
            for (int j = 0; j < 4; j++) {
                const int idx = tid + j * 256, off = (idx >> 3) * PADK + (idx & 7) * 4;
                split_sts(s + DA_HI + off, s + DA_LO + off, pa[j]);
                split_sts(s + DB_HI + off, s + DB_LO + off, pb[j]);
            }
        }
        __syncthreads();
    }

    // epilogue: atomic scatter into out
    #pragma unroll
    for (int mt = 0; mt < 2; mt++) {
        #pragma unroll
        for (int nt = 0; nt < 8; nt++) {
            const int c  = n0 + wn * 64 + nt * 8 + (lane & 3) * 2;
            const int r0 = wm * 32 + mt * 16 + (lane >> 2);
            #pragma unroll
            for (int hf = 0; hf < 2; hf++) {
                const int r = r0 + hf * 8;
                if (m0 + r < cnt) {
                    float* orow = out + (size_t)stok[r] * H + c;
                    atomicAdd(&orow[0], acc[mt][nt][hf * 2 + 0]);
                    atomicAdd(&orow[1], acc[mt][nt][hf * 2 + 1]);
                }
            }
        }
    }
}

// ======================= launch =======================
extern "C" void kernel_launch(void* const* d_in, const int* in_sizes, int n_in,
                              void* d_out, int out_size)
{
    const float* x     = (const float*)d_in[0];
    const float* Wg    = (const float*)d_in[1];
    const float* Wu    = (const float*)d_in[2];
    const float* Wd    = (const float*)d_in[3];
    const float* Wgate = (const float*)d_in[4];
    float* out = (float*)d_out;

    cudaFuncSetAttribute(gateup_mma, cudaFuncAttributeMaxDynamicSharedMemorySize, SMEM_DYN);
    cudaFuncSetAttribute(down_mma,   cudaFuncAttributeMaxDynamicSharedMemorySize, SMEM_DYN);

    void* cnt_ptr = nullptr;
    cudaGetSymbolAddress(&cnt_ptr, g_cnt);
    cudaMemsetAsync(cnt_ptr, 0, E * sizeof(int));
    cudaMemsetAsync(d_out, 0, (size_t)T * H * sizeof(float));

    gate_kernel<<<T, 256>>>(x, Wgate);
    scan_kernel<<<1, 32>>>();

    dim3 g1(II / 64, T / BM, E);     // 16 x 4 x 64
    gateup_mma<<<g1, 256, SMEM_DYN>>>(x, Wg, Wu);

    dim3 g2(H / 128, T / BM, E);     // 16 x 4 x 64
    down_mma<<<g2, 256, SMEM_DYN>>>(Wd, out);
}

// round 8
// speedup vs baseline: 2.5548x; 1.4964x over previous
#include <cuda_runtime.h>
#include <cuda_bf16.h>
#include <stdint.h>
#include <math.h>

#define T    512
#define H    2048
#define II   1024
#define E    64
#define KSEL 8

#define BM   64
#define BK   32
#define PADK 40                      // padded k-stride (elems): 80B, 16B-aligned, ldmatrix conflict-free

// stage layout (bf16 elems). stage = 15360 elems = 30720 B; two stages.
#define STG_ELEMS 15360
#define META_OFF  (2 * STG_ELEMS * 2)          // 61440 B
#define SMEM_DYN  (META_OFF + 1024)

// gateup regions (elem offsets within a stage): A 64x40 hi/lo, G 64x40 hi/lo, U 64x40 hi/lo
#define GA_HI 0
#define GA_LO 2560
#define GG_HI 5120
#define GG_LO 7680
#define GU_HI 10240
#define GU_LO 12800
// down regions: A 64x40 hi/lo, B 128x40 hi/lo
#define DA_HI 0
#define DA_LO 2560
#define DB_HI 5120
#define DB_LO 10240

// -------- device-global scratch (no allocations allowed) --------
__device__ int   g_cnt[E];
__device__ int   g_off[E];
__device__ int   g_tok[E * T];
__device__ float g_prob[E * T];
__device__ float g_act[(size_t)T * KSEL * II];

// ======================= helpers =======================
__device__ __forceinline__ uint32_t smem_u32(const void* p) {
    uint32_t a;
    asm("{ .reg .u64 t; cvta.to.shared.u64 t, %1; cvt.u32.u64 %0, t; }" : "=r"(a) : "l"(p));
    return a;
}

__device__ __forceinline__ void ldm_x4(uint32_t r[4], uint32_t addr) {
    asm volatile("ldmatrix.sync.aligned.m8n8.x4.shared.b16 {%0,%1,%2,%3}, [%4];"
                 : "=r"(r[0]), "=r"(r[1]), "=r"(r[2]), "=r"(r[3]) : "r"(addr));
}
__device__ __forceinline__ void ldm_x2(uint32_t r[2], uint32_t addr) {
    asm volatile("ldmatrix.sync.aligned.m8n8.x2.shared.b16 {%0,%1}, [%2];"
                 : "=r"(r[0]), "=r"(r[1]) : "r"(addr));
}
__device__ __forceinline__ void mma_bf16(float d[4], const uint32_t a[4], const uint32_t b[2]) {
    asm volatile("mma.sync.aligned.m16n8k16.row.col.f32.bf16.bf16.f32 "
                 "{%0,%1,%2,%3}, {%4,%5,%6,%7}, {%8,%9}, {%0,%1,%2,%3};"
                 : "+f"(d[0]), "+f"(d[1]), "+f"(d[2]), "+f"(d[3])
                 : "r"(a[0]), "r"(a[1]), "r"(a[2]), "r"(a[3]), "r"(b[0]), "r"(b[1]));
}

// split fp32x4 -> bf16 hi/lo, store 8B each (padded layout, elem offset)
__device__ __forceinline__ void split_sts(__nv_bfloat16* hi, __nv_bfloat16* lo, float4 v) {
    __nv_bfloat16 h0 = __float2bfloat16(v.x), h1 = __float2bfloat16(v.y);
    __nv_bfloat16 h2 = __float2bfloat16(v.z), h3 = __float2bfloat16(v.w);
    __nv_bfloat16 l0 = __float2bfloat16(v.x - __bfloat162float(h0));
    __nv_bfloat16 l1 = __float2bfloat16(v.y - __bfloat162float(h1));
    __nv_bfloat16 l2 = __float2bfloat16(v.z - __bfloat162float(h2));
    __nv_bfloat16 l3 = __float2bfloat16(v.w - __bfloat162float(h3));
    uint2 hp, lp;
    hp.x = (uint32_t)__bfloat16_as_ushort(h0) | ((uint32_t)__bfloat16_as_ushort(h1) << 16);
    hp.y = (uint32_t)__bfloat16_as_ushort(h2) | ((uint32_t)__bfloat16_as_ushort(h3) << 16);
    lp.x = (uint32_t)__bfloat16_as_ushort(l0) | ((uint32_t)__bfloat16_as_ushort(l1) << 16);
    lp.y = (uint32_t)__bfloat16_as_ushort(l2) | ((uint32_t)__bfloat16_as_ushort(l3) << 16);
    *(uint2*)hi = hp;
    *(uint2*)lo = lp;
}

// ======================= gating =======================
__global__ void gate_kernel(const float* __restrict__ x,
                            const float* __restrict__ Wgate)
{
    __shared__ float sx[H];
    __shared__ float slog[E];
    __shared__ int   s_ids[KSEL];
    __shared__ float s_p[KSEL];

    const int t = blockIdx.x, tid = threadIdx.x;
    for (int i = tid; i < H; i += blockDim.x) sx[i] = x[(size_t)t * H + i];
    __syncthreads();

    const int w = tid >> 5, lane = tid & 31;
    for (int j = 0; j < 8; j++) {
        const int e = w * 8 + j;
        const float* wr = Wgate + (size_t)e * H;
        float s = 0.f;
        for (int h = lane; h < H; h += 32) s += sx[h] * wr[h];
        #pragma unroll
        for (int o = 16; o > 0; o >>= 1) s += __shfl_xor_sync(0xffffffffu, s, o);
        if (lane == 0) slog[e] = s;
    }
    __syncthreads();

    if (tid == 0) {
        float vals[KSEL]; int ids[KSEL];
        for (int j = 0; j < KSEL; j++) {
            float best = -1e30f; int bi = 0;
            for (int e = 0; e < E; e++)
                if (slog[e] > best) { best = slog[e]; bi = e; }
            vals[j] = best; ids[j] = bi; slog[bi] = -1e30f;
        }
        const float m = vals[0];
        float sum = 0.f;
        for (int j = 0; j < KSEL; j++) { vals[j] = expf(vals[j] - m); sum += vals[j]; }
        const float inv = 1.f / sum;
        for (int j = 0; j < KSEL; j++) { s_ids[j] = ids[j]; s_p[j] = vals[j] * inv; }
    }
    __syncthreads();

    if (tid < KSEL) {
        const int e = s_ids[tid];
        const int pos = atomicAdd(&g_cnt[e], 1);
        g_tok[e * T + pos]  = t;
        g_prob[e * T + pos] = s_p[tid];
    }
}

__global__ void scan_kernel()
{
    if (threadIdx.x == 0) {
        int s = 0;
        for (int e = 0; e < E; e++) { g_off[e] = s; s += g_cnt[e]; }
    }
}

// ======================= gate/up: mma.sync GEMM + SwiGLU =======================
// CTA: 64 tokens x 64 i-vals, both Wg & Wu. 8 warps 2(m)x4(i), warp 32m x 16i x 2 mats.
__global__ __launch_bounds__(256, 2) void gateup_mma(const float* __restrict__ x,
                                                     const float* __restrict__ Wg,
                                                     const float* __restrict__ Wu)
{
    extern __shared__ __align__(16) char smraw[];
    __nv_bfloat16* sm = (__nv_bfloat16*)smraw;

    const int e   = blockIdx.z;
    const int cnt = g_cnt[e];
    const int m0  = blockIdx.y * BM;
    if (m0 >= cnt) return;
    const int i0   = blockIdx.x * 64;
    const int base = g_off[e];
    const int tid = threadIdx.x, wid = tid >> 5, lane = tid & 31;

    int*   stok = (int*)(smraw + META_OFF);
    float* sp   = (float*)(smraw + META_OFF + 256);
    if (tid < BM) {
        const int mm = min(m0 + tid, cnt - 1);
        stok[tid] = g_tok[e * T + mm];
        sp[tid]   = (m0 + tid < cnt) ? g_prob[e * T + m0 + tid] : 0.f;
    }
    __syncthreads();

    const float* WgE = Wg + ((size_t)e * II + i0) * H;
    const float* WuE = Wu + ((size_t)e * II + i0) * H;

    const int wm = wid >> 2;   // 0..1
    const int wn = wid & 3;    // 0..3

    float ag[2][2][4] = {}, au[2][2][4] = {};
    float4 pa[2], pg[2], pu[2];

    const int NCH = H / BK;    // 64

    // prefetch + fill stage 0
    {
        #pragma unroll
        for (int j = 0; j < 2; j++) {
            const int idx = tid + j * 256, r = idx >> 3, c = idx & 7;
            pa[j] = *(const float4*)(x + (size_t)stok[r] * H + c * 4);
            pg[j] = *(const float4*)(WgE + (size_t)r * H + c * 4);
            pu[j] = *(const float4*)(WuE + (size_t)r * H + c * 4);
        }
        #pragma unroll
        for (int j = 0; j < 2; j++) {
            const int idx = tid + j * 256, off = (idx >> 3) * PADK + (idx & 7) * 4;
            split_sts(sm + GA_HI + off, sm + GA_LO + off, pa[j]);
            split_sts(sm + GG_HI + off, sm + GG_LO + off, pg[j]);
            split_sts(sm + GU_HI + off, sm + GU_LO + off, pu[j]);
        }
        __syncthreads();
    }

    for (int ch = 0; ch < NCH; ch++) {
        if (ch + 1 < NCH) {
            const int k0 = (ch + 1) * BK;
            #pragma unroll
            for (int j = 0; j < 2; j++) {
                const int idx = tid + j * 256, r = idx >> 3, c = idx & 7;
                pa[j] = *(const float4*)(x + (size_t)stok[r] * H + k0 + c * 4);
                pg[j] = *(const float4*)(WgE + (size_t)r * H + k0 + c * 4);
                pu[j] = *(const float4*)(WuE + (size_t)r * H + k0 + c * 4);
            }
        }

        // compute on stage ch&1
        {
            const uint32_t sbase = smem_u32(sm + (ch & 1) * STG_ELEMS);
            #pragma unroll
            for (int k16 = 0; k16 < BK; k16 += 16) {
                uint32_t ah[4], al[4];
                {
                    const int row = wm * 32 + (lane & 15);
                    const int col = k16 + ((lane >> 4) << 3);
                    const uint32_t off = (uint32_t)(row * PADK + col) * 2;
                    ldm_x4(ah, sbase + GA_HI * 2 + off);
                    ldm_x4(al, sbase + GA_LO * 2 + off);
                }
                #pragma unroll
                for (int it = 0; it < 2; it++) {
                    const int rowb = wn * 16 + it * 8 + (lane & 7);
                    const int colb = k16 + (((lane >> 3) & 1) << 3);
                    const uint32_t offb = (uint32_t)(rowb * PADK + colb) * 2;
                    uint32_t bgh[2], bgl[2], buh[2], bul[2];
                    ldm_x2(bgh, sbase + GG_HI * 2 + offb);
                    ldm_x2(bgl, sbase + GG_LO * 2 + offb);
                    ldm_x2(buh, sbase + GU_HI * 2 + offb);
                    ldm_x2(bul, sbase + GU_LO * 2 + offb);
                    // ah/al cover two 16-row m-tiles via frag pairs
                    uint32_t a0h[4] = {ah[0], ah[1], ah[2], ah[3]};
                    mma_bf16(ag[0][it], a0h, bgh);
                    mma_bf16(ag[0][it], a0h, bgl);
                    uint32_t a0l[4] = {al[0], al[1], al[2], al[3]};
                    mma_bf16(ag[0][it], a0l, bgh);
                    mma_bf16(au[0][it], a0h, buh);
                    mma_bf16(au[0][it], a0h, bul);
                    mma_bf16(au[0][it], a0l, buh);
                }
                // second m-tile (rows wm*32+16..31)
                uint32_t ah2[4], al2[4];
                {
                    const int row = wm * 32 + 16 + (lane & 15);
                    const int col = k16 + ((lane >> 4) << 3);
                    const uint32_t off = (uint32_t)(row * PADK + col) * 2;
                    ldm_x4(ah2, sbase + GA_HI * 2 + off);
                    ldm_x4(al2, sbase + GA_LO * 2 + off);
                }
                #pragma unroll
                for (int it = 0; it < 2; it++) {
                    const int rowb = wn * 16 + it * 8 + (lane & 7);
                    const int colb = k16 + (((lane >> 3) & 1) << 3);
                    const uint32_t offb = (uint32_t)(rowb * PADK + colb) * 2;
                    uint32_t bgh[2], bgl[2], buh[2], bul[2];
                    ldm_x2(bgh, sbase + GG_HI * 2 + offb);
                    ldm_x2(bgl, sbase + GG_LO * 2 + offb);
                    ldm_x2(buh, sbase + GU_HI * 2 + offb);
                    ldm_x2(bul, sbase + GU_LO * 2 + offb);
                    mma_bf16(ag[1][it], ah2, bgh);
                    mma_bf16(ag[1][it], ah2, bgl);
                    mma_bf16(ag[1][it], al2, bgh);
                    mma_bf16(au[1][it], ah2, buh);
                    mma_bf16(au[1][it], ah2, bul);
                    mma_bf16(au[1][it], al2, buh);
                }
            }
        }

        if (ch + 1 < NCH) {
            __nv_bfloat16* s = sm + ((ch + 1) & 1) * STG_ELEMS;
            #pragma unroll
            for (int j = 0; j < 2; j++) {
                const int idx = tid + j * 256, off = (idx >> 3) * PADK + (idx & 7) * 4;
                split_sts(s + GA_HI + off, s + GA_LO + off, pa[j]);
                split_sts(s + GG_HI + off, s + GG_LO + off, pg[j]);
                split_sts(s + GU_HI + off, s + GU_LO + off, pu[j]);
            }
        }
        __syncthreads();
    }

    // epilogue: silu(hg)*hu*p -> g_act
    #pragma unroll
    for (int mt = 0; mt < 2; mt++) {
        #pragma unroll
        for (int it = 0; it < 2; it++) {
            const int c  = i0 + wn * 16 + it * 8 + (lane & 3) * 2;
            const int r0 = wm * 32 + mt * 16 + (lane >> 2);
            #pragma unroll
            for (int hf = 0; hf < 2; hf++) {
                const int r = r0 + hf * 8;
                if (m0 + r < cnt) {
                    const float p = sp[r];
                    const float hg0 = ag[mt][it][hf * 2 + 0], hu0 = au[mt][it][hf * 2 + 0];
                    const float hg1 = ag[mt][it][hf * 2 + 1], hu1 = au[mt][it][hf * 2 + 1];
                    float2 v;
                    v.x = hg0 / (1.f + expf(-hg0)) * hu0 * p;
                    v.y = hg1 / (1.f + expf(-hg1)) * hu1 * p;
                    *(float2*)(g_act + (size_t)(base + m0 + r) * II + c) = v;
                }
            }
        }
    }
}

// ======================= down: mma.sync GEMM + scatter =======================
// CTA: 64 rows x 128 h-cols. 8 warps 2(m)x4(n), warp 32m x 32n.
__global__ __launch_bounds__(256, 2) void down_mma(const float* __restrict__ Wd,
                                                   float* __restrict__ out)
{
    extern __shared__ __align__(16) char smraw[];
    __nv_bfloat16* sm = (__nv_bfloat16*)smraw;

    const int e   = blockIdx.z;
    const int cnt = g_cnt[e];
    const int m0  = blockIdx.y * BM;
    if (m0 >= cnt) return;
    const int n0   = blockIdx.x * 128;
    const int base = g_off[e];
    const int tid = threadIdx.x, wid = tid >> 5, lane = tid & 31;

    int* stok = (int*)(smraw + META_OFF);
    int* srow = (int*)(smraw + META_OFF + 256);
    if (tid < BM) {
        const int mm = min(m0 + tid, cnt - 1);
        stok[tid] = g_tok[e * T + mm];
        srow[tid] = base + mm;
    }
    __syncthreads();

    const float* WdE = Wd + ((size_t)e * H + n0) * II;

    const int wm = wid >> 2;   // 0..1
    const int wn = wid & 3;    // 0..3

    float acc[2][4][4] = {};
    float4 pa[2], pb[4];

    const int NCH = II / BK;   // 32

    {
        #pragma unroll
        for (int j = 0; j < 2; j++) {
            const int idx = tid + j * 256, r = idx >> 3, c = idx & 7;
            pa[j] = *(const float4*)(g_act + (size_t)srow[r] * II + c * 4);
        }
        #pragma unroll
        for (int j = 0; j < 4; j++) {
            const int idx = tid + j * 256, r = idx >> 3, c = idx & 7;
            pb[j] = *(const float4*)(WdE + (size_t)r * II + c * 4);
        }
        #pragma unroll
        for (int j = 0; j < 2; j++) {
            const int idx = tid + j * 256, off = (idx >> 3) * PADK + (idx & 7) * 4;
            split_sts(sm + DA_HI + off, sm + DA_LO + off, pa[j]);
        }
        #pragma unroll
        for (int j = 0; j < 4; j++) {
            const int idx = tid + j * 256, off = (idx >> 3) * PADK + (idx & 7) * 4;
            split_sts(sm + DB_HI + off, sm + DB_LO + off, pb[j]);
        }
        __syncthreads();
    }

    for (int ch = 0; ch < NCH; ch++) {
        if (ch + 1 < NCH) {
            const int k0 = (ch + 1) * BK;
            #pragma unroll
            for (int j = 0; j < 2; j++) {
                const int idx = tid + j * 256, r = idx >> 3, c = idx & 7;
                pa[j] = *(const float4*)(g_act + (size_t)srow[r] * II + k0 + c * 4);
            }
            #pragma unroll
            for (int j = 0; j < 4; j++) {
                const int idx = tid + j * 256, r = idx >> 3, c = idx & 7;
                pb[j] = *(const float4*)(WdE + (size_t)r * II + k0 + c * 4);
            }
        }

        {
            const uint32_t sbase = smem_u32(sm + (ch & 1) * STG_ELEMS);
            #pragma unroll
            for (int k16 = 0; k16 < BK; k16 += 16) {
                #pragma unroll
                for (int mt = 0; mt < 2; mt++) {
                    uint32_t ah[4], al[4];
                    const int row = wm * 32 + mt * 16 + (lane & 15);
                    const int col = k16 + ((lane >> 4) << 3);
                    const uint32_t off = (uint32_t)(row * PADK + col) * 2;
                    ldm_x4(ah, sbase + DA_HI * 2 + off);
                    ldm_x4(al, sbase + DA_LO * 2 + off);
                    #pragma unroll
                    for (int nt = 0; nt < 4; nt++) {
                        const int rowb = wn * 32 + nt * 8 + (lane & 7);
                        const int colb = k16 + (((lane >> 3) & 1) << 3);
                        const uint32_t offb = (uint32_t)(rowb * PADK + colb) * 2;
                        uint32_t bh[2], bl[2];
                        ldm_x2(bh, sbase + DB_HI * 2 + offb);
                        ldm_x2(bl, sbase + DB_LO * 2 + offb);
                        mma_bf16(acc[mt][nt], ah, bh);
                        mma_bf16(acc[mt][nt], ah, bl);
                        mma_bf16(acc[mt][nt], al, bh);
                    }
                }
            }
        }

        if (ch + 1 < NCH) {
            __nv_bfloat16* s = sm + ((ch + 1) & 1) * STG_ELEMS;
            #pragma unroll
            for (int j = 0; j < 2; j++) {
                const int idx = tid + j * 256, off = (idx >> 3) * PADK + (idx & 7) * 4;
                split_sts(s + DA_HI + off, s + DA_LO + off, pa[j]);
            }
            #pragma unroll
            for (int j = 0; j < 4; j++) {
                const int idx = tid + j * 256, off = (idx >> 3) * PADK + (idx & 7) * 4;
                split_sts(s + DB_HI + off, s + DB_LO + off, pb[j]);
            }
        }
        __syncthreads();
    }

    // epilogue: atomic scatter into out
    #pragma unroll
    for (int mt = 0; mt < 2; mt++) {
        #pragma unroll
        for (int nt = 0; nt < 4; nt++) {
            const int c  = n0 + wn * 32 + nt * 8 + (lane & 3) * 2;
            const int r0 = wm * 32 + mt * 16 + (lane >> 2);
            #pragma unroll
            for (int hf = 0; hf < 2; hf++) {
                const int r = r0 + hf * 8;
                if (m0 + r < cnt) {
                    float* orow = out + (size_t)stok[r] * H + c;
                    atomicAdd(&orow[0], acc[mt][nt][hf * 2 + 0]);
                    atomicAdd(&orow[1], acc[mt][nt][hf * 2 + 1]);
                }
            }
        }
    }
}

// ======================= launch =======================
extern "C" void kernel_launch(void* const* d_in, const int* in_sizes, int n_in,
                              void* d_out, int out_size)
{
    const float* x     = (const float*)d_in[0];
    const float* Wg    = (const float*)d_in[1];
    const float* Wu    = (const float*)d_in[2];
    const float* Wd    = (const float*)d_in[3];
    const float* Wgate = (const float*)d_in[4];
    float* out = (float*)d_out;

    cudaFuncSetAttribute(gateup_mma, cudaFuncAttributeMaxDynamicSharedMemorySize, SMEM_DYN);
    cudaFuncSetAttribute(down_mma,   cudaFuncAttributeMaxDynamicSharedMemorySize, SMEM_DYN);

    void* cnt_ptr = nullptr;
    cudaGetSymbolAddress(&cnt_ptr, g_cnt);
    cudaMemsetAsync(cnt_ptr, 0, E * sizeof(int));
    cudaMemsetAsync(d_out, 0, (size_t)T * H * sizeof(float));

    gate_kernel<<<T, 256>>>(x, Wgate);
    scan_kernel<<<1, 32>>>();

    dim3 g1(II / 64, T / BM, E);     // 16 x 8 x 64
    gateup_mma<<<g1, 256, SMEM_DYN>>>(x, Wg, Wu);

    dim3 g2(H / 128, T / BM, E);     // 16 x 8 x 64
    down_mma<<<g2, 256, SMEM_DYN>>>(Wd, out);
}

// round 9
// speedup vs baseline: 2.5691x; 1.0056x over previous
#include <cuda_runtime.h>
#include <cuda_bf16.h>
#include <stdint.h>
#include <math.h>

#define T    512
#define H    2048
#define II   1024
#define E    64
#define KSEL 8

#define BM   64
#define BK   32
#define PADK 40                      // padded k-stride (elems): 80B, 16B-aligned, ldmatrix conflict-free

// stage layout (bf16 elems). stage = 15360 elems = 30720 B; two stages.
#define STG_ELEMS 15360
#define META_OFF  (2 * STG_ELEMS * 2)          // 61440 B
#define SMEM_DYN  (META_OFF + 1024)

// gateup regions (elem offsets within a stage): A 64x40 hi/lo, G 64x40 hi/lo, U 64x40 hi/lo
#define GA_HI 0
#define GA_LO 2560
#define GG_HI 5120
#define GG_LO 7680
#define GU_HI 10240
#define GU_LO 12800
// down regions: A 64x40 hi/lo, B 128x40 hi/lo
#define DA_HI 0
#define DA_LO 2560
#define DB_HI 5120
#define DB_LO 10240

// -------- device-global scratch (no allocations allowed) --------
__device__ int   g_cnt[E];
__device__ int   g_off[E];
__device__ int   g_tok[E * T];
__device__ float g_prob[E * T];
__device__ float g_act[(size_t)T * KSEL * II];

// ======================= helpers =======================
__device__ __forceinline__ uint32_t smem_u32(const void* p) {
    uint32_t a;
    asm("{ .reg .u64 t; cvta.to.shared.u64 t, %1; cvt.u32.u64 %0, t; }" : "=r"(a) : "l"(p));
    return a;
}

__device__ __forceinline__ void ldm_x4(uint32_t r[4], uint32_t addr) {
    asm volatile("ldmatrix.sync.aligned.m8n8.x4.shared.b16 {%0,%1,%2,%3}, [%4];"
                 : "=r"(r[0]), "=r"(r[1]), "=r"(r[2]), "=r"(r[3]) : "r"(addr));
}
__device__ __forceinline__ void mma_bf16(float d[4], const uint32_t a[4], const uint32_t b0, const uint32_t b1) {
    asm volatile("mma.sync.aligned.m16n8k16.row.col.f32.bf16.bf16.f32 "
                 "{%0,%1,%2,%3}, {%4,%5,%6,%7}, {%8,%9}, {%0,%1,%2,%3};"
                 : "+f"(d[0]), "+f"(d[1]), "+f"(d[2]), "+f"(d[3])
                 : "r"(a[0]), "r"(a[1]), "r"(a[2]), "r"(a[3]), "r"(b0), "r"(b1));
}

// split fp32x4 -> bf16 hi/lo, store 8B each (padded layout, elem offset)
__device__ __forceinline__ void split_sts(__nv_bfloat16* hi, __nv_bfloat16* lo, float4 v) {
    __nv_bfloat16 h0 = __float2bfloat16(v.x), h1 = __float2bfloat16(v.y);
    __nv_bfloat16 h2 = __float2bfloat16(v.z), h3 = __float2bfloat16(v.w);
    __nv_bfloat16 l0 = __float2bfloat16(v.x - __bfloat162float(h0));
    __nv_bfloat16 l1 = __float2bfloat16(v.y - __bfloat162float(h1));
    __nv_bfloat16 l2 = __float2bfloat16(v.z - __bfloat162float(h2));
    __nv_bfloat16 l3 = __float2bfloat16(v.w - __bfloat162float(h3));
    uint2 hp, lp;
    hp.x = (uint32_t)__bfloat16_as_ushort(h0) | ((uint32_t)__bfloat16_as_ushort(h1) << 16);
    hp.y = (uint32_t)__bfloat16_as_ushort(h2) | ((uint32_t)__bfloat16_as_ushort(h3) << 16);
    lp.x = (uint32_t)__bfloat16_as_ushort(l0) | ((uint32_t)__bfloat16_as_ushort(l1) << 16);
    lp.y = (uint32_t)__bfloat16_as_ushort(l2) | ((uint32_t)__bfloat16_as_ushort(l3) << 16);
    *(uint2*)hi = hp;
    *(uint2*)lo = lp;
}

// ======================= gating =======================
__global__ void gate_kernel(const float* __restrict__ x,
                            const float* __restrict__ Wgate)
{
    __shared__ float sx[H];
    __shared__ float slog[E];
    __shared__ int   s_ids[KSEL];
    __shared__ float s_p[KSEL];

    const int t = blockIdx.x, tid = threadIdx.x;
    for (int i = tid; i < H; i += blockDim.x) sx[i] = x[(size_t)t * H + i];
    __syncthreads();

    const int w = tid >> 5, lane = tid & 31;
    for (int j = 0; j < 8; j++) {
        const int e = w * 8 + j;
        const float* wr = Wgate + (size_t)e * H;
        float s = 0.f;
        for (int h = lane; h < H; h += 32) s += sx[h] * wr[h];
        #pragma unroll
        for (int o = 16; o > 0; o >>= 1) s += __shfl_xor_sync(0xffffffffu, s, o);
        if (lane == 0) slog[e] = s;
    }
    __syncthreads();

    if (tid == 0) {
        float vals[KSEL]; int ids[KSEL];
        for (int j = 0; j < KSEL; j++) {
            float best = -1e30f; int bi = 0;
            for (int e = 0; e < E; e++)
                if (slog[e] > best) { best = slog[e]; bi = e; }
            vals[j] = best; ids[j] = bi; slog[bi] = -1e30f;
        }
        const float m = vals[0];
        float sum = 0.f;
        for (int j = 0; j < KSEL; j++) { vals[j] = expf(vals[j] - m); sum += vals[j]; }
        const float inv = 1.f / sum;
        for (int j = 0; j < KSEL; j++) { s_ids[j] = ids[j]; s_p[j] = vals[j] * inv; }
    }
    __syncthreads();

    if (tid < KSEL) {
        const int e = s_ids[tid];
        const int pos = atomicAdd(&g_cnt[e], 1);
        g_tok[e * T + pos]  = t;
        g_prob[e * T + pos] = s_p[tid];
    }
}

__global__ void scan_kernel()
{
    if (threadIdx.x == 0) {
        int s = 0;
        for (int e = 0; e < E; e++) { g_off[e] = s; s += g_cnt[e]; }
    }
}

// ======================= gate/up: mma.sync GEMM + SwiGLU =======================
// CTA: 64 tokens x 64 i-vals, both Wg & Wu. 8 warps 2(m)x4(i), warp 32m x 16i x 2 mats.
__global__ __launch_bounds__(256, 2) void gateup_mma(const float* __restrict__ x,
                                                     const float* __restrict__ Wg,
                                                     const float* __restrict__ Wu)
{
    extern __shared__ __align__(16) char smraw[];
    __nv_bfloat16* sm = (__nv_bfloat16*)smraw;

    const int e   = blockIdx.z;
    const int cnt = g_cnt[e];
    const int m0  = blockIdx.y * BM;
    if (m0 >= cnt) return;
    const int i0   = blockIdx.x * 64;
    const int base = g_off[e];
    const int tid = threadIdx.x, wid = tid >> 5, lane = tid & 31;

    int*   stok = (int*)(smraw + META_OFF);
    float* sp   = (float*)(smraw + META_OFF + 256);
    if (tid < BM) {
        const int mm = min(m0 + tid, cnt - 1);
        stok[tid] = g_tok[e * T + mm];
        sp[tid]   = (m0 + tid < cnt) ? g_prob[e * T + m0 + tid] : 0.f;
    }
    __syncthreads();

    const float* WgE = Wg + ((size_t)e * II + i0) * H;
    const float* WuE = Wu + ((size_t)e * II + i0) * H;

    const int wm = wid >> 2;   // 0..1
    const int wn = wid & 3;    // 0..3

    // ldmatrix lane offsets (elem units), fixed across k loop
    const uint32_t offA0 = (uint32_t)((wm * 32 + (lane & 15)) * PADK + ((lane >> 4) << 3));
    const uint32_t offA1 = offA0 + 16 * PADK;
    const uint32_t offB  = (uint32_t)((wn * 16 + ((lane >> 4) << 3) + (lane & 7)) * PADK
                                      + (((lane >> 3) & 1) << 3));

    float ag[2][2][4] = {}, au[2][2][4] = {};
    float4 pa[2], pg[2], pu[2];

    const int NCH = H / BK;    // 64

    // prefetch + fill stage 0
    {
        #pragma unroll
        for (int j = 0; j < 2; j++) {
            const int idx = tid + j * 256, r = idx >> 3, c = idx & 7;
            pa[j] = *(const float4*)(x + (size_t)stok[r] * H + c * 4);
            pg[j] = *(const float4*)(WgE + (size_t)r * H + c * 4);
            pu[j] = *(const float4*)(WuE + (size_t)r * H + c * 4);
        }
        #pragma unroll
        for (int j = 0; j < 2; j++) {
            const int idx = tid + j * 256, off = (idx >> 3) * PADK + (idx & 7) * 4;
            split_sts(sm + GA_HI + off, sm + GA_LO + off, pa[j]);
            split_sts(sm + GG_HI + off, sm + GG_LO + off, pg[j]);
            split_sts(sm + GU_HI + off, sm + GU_LO + off, pu[j]);
        }
        __syncthreads();
    }

    for (int ch = 0; ch < NCH; ch++) {
        if (ch + 1 < NCH) {
            const int k0 = (ch + 1) * BK;
            #pragma unroll
            for (int j = 0; j < 2; j++) {
                const int idx = tid + j * 256, r = idx >> 3, c = idx & 7;
                pa[j] = *(const float4*)(x + (size_t)stok[r] * H + k0 + c * 4);
                pg[j] = *(const float4*)(WgE + (size_t)r * H + k0 + c * 4);
                pu[j] = *(const float4*)(WuE + (size_t)r * H + k0 + c * 4);
            }
        }

        // compute on stage ch&1
        {
            const uint32_t sbase = smem_u32(sm + (ch & 1) * STG_ELEMS);
            #pragma unroll
            for (int k16 = 0; k16 < BK; k16 += 16) {
                const uint32_t kb = (uint32_t)k16 * 2;
                // A fragments: 2 m-tiles, hi/lo
                uint32_t ah[2][4], al[2][4];
                ldm_x4(ah[0], sbase + (GA_HI * 2) + (offA0 * 2) + kb);
                ldm_x4(al[0], sbase + (GA_LO * 2) + (offA0 * 2) + kb);
                ldm_x4(ah[1], sbase + (GA_HI * 2) + (offA1 * 2) + kb);
                ldm_x4(al[1], sbase + (GA_LO * 2) + (offA1 * 2) + kb);
                // B fragments: x4 covers both it-tiles (16 i-rows), g & u, hi/lo
                uint32_t gh[4], gl[4], uh[4], ul[4];
                ldm_x4(gh, sbase + (GG_HI * 2) + (offB * 2) + kb);
                ldm_x4(gl, sbase + (GG_LO * 2) + (offB * 2) + kb);
                ldm_x4(uh, sbase + (GU_HI * 2) + (offB * 2) + kb);
                ldm_x4(ul, sbase + (GU_LO * 2) + (offB * 2) + kb);

                #pragma unroll
                for (int mt = 0; mt < 2; mt++) {
                    #pragma unroll
                    for (int it = 0; it < 2; it++) {
                        mma_bf16(ag[mt][it], ah[mt], gh[it * 2], gh[it * 2 + 1]);
                        mma_bf16(ag[mt][it], ah[mt], gl[it * 2], gl[it * 2 + 1]);
                        mma_bf16(ag[mt][it], al[mt], gh[it * 2], gh[it * 2 + 1]);
                        mma_bf16(au[mt][it], ah[mt], uh[it * 2], uh[it * 2 + 1]);
                        mma_bf16(au[mt][it], ah[mt], ul[it * 2], ul[it * 2 + 1]);
                        mma_bf16(au[mt][it], al[mt], uh[it * 2], uh[it * 2 + 1]);
                    }
                }
            }
        }

        if (ch + 1 < NCH) {
            __nv_bfloat16* s = sm + ((ch + 1) & 1) * STG_ELEMS;
            #pragma unroll
            for (int j = 0; j < 2; j++) {
                const int idx = tid + j * 256, off = (idx >> 3) * PADK + (idx & 7) * 4;
                split_sts(s + GA_HI + off, s + GA_LO + off, pa[j]);
                split_sts(s + GG_HI + off, s + GG_LO + off, pg[j]);
                split_sts(s + GU_HI + off, s + GU_LO + off, pu[j]);
            }
        }
        __syncthreads();
    }

    // epilogue: silu(hg)*hu*p -> g_act
    #pragma unroll
    for (int mt = 0; mt < 2; mt++) {
        #pragma unroll
        for (int it = 0; it < 2; it++) {
            const int c  = i0 + wn * 16 + it * 8 + (lane & 3) * 2;
            const int r0 = wm * 32 + mt * 16 + (lane >> 2);
            #pragma unroll
            for (int hf = 0; hf < 2; hf++) {
                const int r = r0 + hf * 8;
                if (m0 + r < cnt) {
                    const float p = sp[r];
                    const float hg0 = ag[mt][it][hf * 2 + 0], hu0 = au[mt][it][hf * 2 + 0];
                    const float hg1 = ag[mt][it][hf * 2 + 1], hu1 = au[mt][it][hf * 2 + 1];
                    float2 v;
                    v.x = hg0 / (1.f + expf(-hg0)) * hu0 * p;
                    v.y = hg1 / (1.f + expf(-hg1)) * hu1 * p;
                    *(float2*)(g_act + (size_t)(base + m0 + r) * II + c) = v;
                }
            }
        }
    }
}

// ======================= down: mma.sync GEMM + scatter =======================
// CTA: 64 rows x 128 h-cols. 8 warps 2(m)x4(n), warp 32m x 32n.
__global__ __launch_bounds__(256, 2) void down_mma(const float* __restrict__ Wd,
                                                   float* __restrict__ out)
{
    extern __shared__ __align__(16) char smraw[];
    __nv_bfloat16* sm = (__nv_bfloat16*)smraw;

    const int e   = blockIdx.z;
    const int cnt = g_cnt[e];
    const int m0  = blockIdx.y * BM;
    if (m0 >= cnt) return;
    const int n0   = blockIdx.x * 128;
    const int base = g_off[e];
    const int tid = threadIdx.x, wid = tid >> 5, lane = tid & 31;

    int* stok = (int*)(smraw + META_OFF);
    int* srow = (int*)(smraw + META_OFF + 256);
    if (tid < BM) {
        const int mm = min(m0 + tid, cnt - 1);
        stok[tid] = g_tok[e * T + mm];
        srow[tid] = base + mm;
    }
    __syncthreads();

    const float* WdE = Wd + ((size_t)e * H + n0) * II;

    const int wm = wid >> 2;   // 0..1
    const int wn = wid & 3;    // 0..3

    const uint32_t offA0 = (uint32_t)((wm * 32 + (lane & 15)) * PADK + ((lane >> 4) << 3));
    const uint32_t offA1 = offA0 + 16 * PADK;
    const uint32_t offB0 = (uint32_t)((wn * 32 + ((lane >> 4) << 3) + (lane & 7)) * PADK
                                      + (((lane >> 3) & 1) << 3));
    const uint32_t offB1 = offB0 + 16 * PADK;

    float acc[2][4][4] = {};
    float4 pa[2], pb[4];

    const int NCH = II / BK;   // 32

    {
        #pragma unroll
        for (int j = 0; j < 2; j++) {
            const int idx = tid + j * 256, r = idx >> 3, c = idx & 7;
            pa[j] = *(const float4*)(g_act + (size_t)srow[r] * II + c * 4);
        }
        #pragma unroll
        for (int j = 0; j < 4; j++) {
            const int idx = tid + j * 256, r = idx >> 3, c = idx & 7;
            pb[j] = *(const float4*)(WdE + (size_t)r * II + c * 4);
        }
        #pragma unroll
        for (int j = 0; j < 2; j++) {
            const int idx = tid + j * 256, off = (idx >> 3) * PADK + (idx & 7) * 4;
            split_sts(sm + DA_HI + off, sm + DA_LO + off, pa[j]);
        }
        #pragma unroll
        for (int j = 0; j < 4; j++) {
            const int idx = tid + j * 256, off = (idx >> 3) * PADK + (idx & 7) * 4;
            split_sts(sm + DB_HI + off, sm + DB_LO + off, pb[j]);
        }
        __syncthreads();
    }

    for (int ch = 0; ch < NCH; ch++) {
        if (ch + 1 < NCH) {
            const int k0 = (ch + 1) * BK;
            #pragma unroll
            for (int j = 0; j < 2; j++) {
                const int idx = tid + j * 256, r = idx >> 3, c = idx & 7;
                pa[j] = *(const float4*)(g_act + (size_t)srow[r] * II + k0 + c * 4);
            }
            #pragma unroll
            for (int j = 0; j < 4; j++) {
                const int idx = tid + j * 256, r = idx >> 3, c = idx & 7;
                pb[j] = *(const float4*)(WdE + (size_t)r * II + k0 + c * 4);
            }
        }

        {
            const uint32_t sbase = smem_u32(sm + (ch & 1) * STG_ELEMS);
            #pragma unroll
            for (int k16 = 0; k16 < BK; k16 += 16) {
                const uint32_t kb = (uint32_t)k16 * 2;
                // A fragments (2 m-tiles, hi/lo)
                uint32_t ah[2][4], al[2][4];
                ldm_x4(ah[0], sbase + (DA_HI * 2) + (offA0 * 2) + kb);
                ldm_x4(al[0], sbase + (DA_LO * 2) + (offA0 * 2) + kb);
                ldm_x4(ah[1], sbase + (DA_HI * 2) + (offA1 * 2) + kb);
                ldm_x4(al[1], sbase + (DA_LO * 2) + (offA1 * 2) + kb);
                // B fragments: two x4 pairs cover nt 0..3, hi/lo
                uint32_t bh[2][4], bl[2][4];
                ldm_x4(bh[0], sbase + (DB_HI * 2) + (offB0 * 2) + kb);
                ldm_x4(bl[0], sbase + (DB_LO * 2) + (offB0 * 2) + kb);
                ldm_x4(bh[1], sbase + (DB_HI * 2) + (offB1 * 2) + kb);
                ldm_x4(bl[1], sbase + (DB_LO * 2) + (offB1 * 2) + kb);

                #pragma unroll
                for (int mt = 0; mt < 2; mt++) {
                    #pragma unroll
                    for (int nt = 0; nt < 4; nt++) {
                        const int p = nt >> 1, q = (nt & 1) * 2;
                        mma_bf16(acc[mt][nt], ah[mt], bh[p][q], bh[p][q + 1]);
                        mma_bf16(acc[mt][nt], ah[mt], bl[p][q], bl[p][q + 1]);
                        mma_bf16(acc[mt][nt], al[mt], bh[p][q], bh[p][q + 1]);
                    }
                }
            }
        }

        if (ch + 1 < NCH) {
            __nv_bfloat16* s = sm + ((ch + 1) & 1) * STG_ELEMS;
            #pragma unroll
            for (int j = 0; j < 2; j++) {
                const int idx = tid + j * 256, off = (idx >> 3) * PADK + (idx & 7) * 4;
                split_sts(s + DA_HI + off, s + DA_LO + off, pa[j]);
            }
            #pragma unroll
            for (int j = 0; j < 4; j++) {
                const int idx = tid + j * 256, off = (idx >> 3) * PADK + (idx & 7) * 4;
                split_sts(s + DB_HI + off, s + DB_LO + off, pb[j]);
            }
        }
        __syncthreads();
    }

    // epilogue: atomic scatter into out
    #pragma unroll
    for (int mt = 0; mt < 2; mt++) {
        #pragma unroll
        for (int nt = 0; nt < 4; nt++) {
            const int c  = n0 + wn * 32 + nt * 8 + (lane & 3) * 2;
            const int r0 = wm * 32 + mt * 16 + (lane >> 2);
            #pragma unroll
            for (int hf = 0; hf < 2; hf++) {
                const int r = r0 + hf * 8;
                if (m0 + r < cnt) {
                    float* orow = out + (size_t)stok[r] * H + c;
                    atomicAdd(&orow[0], acc[mt][nt][hf * 2 + 0]);
                    atomicAdd(&orow[1], acc[mt][nt][hf * 2 + 1]);
                }
            }
        }
    }
}

// ======================= launch =======================
extern "C" void kernel_launch(void* const* d_in, const int* in_sizes, int n_in,
                              void* d_out, int out_size)
{
    const float* x     = (const float*)d_in[0];
    const float* Wg    = (const float*)d_in[1];
    const float* Wu    = (const float*)d_in[2];
    const float* Wd    = (const float*)d_in[3];
    const float* Wgate = (const float*)d_in[4];
    float* out = (float*)d_out;

    cudaFuncSetAttribute(gateup_mma, cudaFuncAttributeMaxDynamicSharedMemorySize, SMEM_DYN);
    cudaFuncSetAttribute(down_mma,   cudaFuncAttributeMaxDynamicSharedMemorySize, SMEM_DYN);

    void* cnt_ptr = nullptr;
    cudaGetSymbolAddress(&cnt_ptr, g_cnt);
    cudaMemsetAsync(cnt_ptr, 0, E * sizeof(int));
    cudaMemsetAsync(d_out, 0, (size_t)T * H * sizeof(float));

    gate_kernel<<<T, 256>>>(x, Wgate);
    scan_kernel<<<1, 32>>>();

    dim3 g1(II / 64, T / BM, E);     // 16 x 8 x 64
    gateup_mma<<<g1, 256, SMEM_DYN>>>(x, Wg, Wu);

    dim3 g2(H / 128, T / BM, E);     // 16 x 8 x 64
    down_mma<<<g2, 256, SMEM_DYN>>>(Wd, out);
}